// round 7
// baseline (speedup 1.0000x reference)
#include <cuda_runtime.h>
#include <cstdint>
#include <math.h>

#define B    64
#define C    768
#define HW   576
#define NM   50
#define NSEL (B*NM)   // 3200
#define EPSV 1e-5f
#define KC   32
#define NCH  (C/KC)    // 24
#define NCH2 (NSEL/KC) // 100

typedef unsigned long long ull;

// ---------------- scratch ----------------
__device__ float  g_a2[B*HW], g_b2[B*HW];
__device__ ull    g_key[2][B*HW];
__device__ int    g_sel_in[2][NSEL];
__device__ int    g_sel_c [2][NSEL];
__device__ float  g_X[4][(size_t)NSEL*C];
__device__ float  g_S[6][(size_t)C*C];
__device__ float  g_csp[6][16][C];
__device__ float  g_colsum[6][C];
__device__ double g_acc[32];

// ---------------- helpers ----------------
__device__ __forceinline__ void mma_tf32(float c[4], const uint32_t a[4], const uint32_t b[2]) {
    asm volatile(
        "mma.sync.aligned.m16n8k8.row.col.f32.tf32.tf32.f32 "
        "{%0,%1,%2,%3}, {%4,%5,%6,%7}, {%8,%9}, {%0,%1,%2,%3};"
        : "+f"(c[0]), "+f"(c[1]), "+f"(c[2]), "+f"(c[3])
        : "r"(a[0]), "r"(a[1]), "r"(a[2]), "r"(a[3]), "r"(b[0]), "r"(b[1]));
}
#define CP_A16(d, s) asm volatile("cp.async.ca.shared.global [%0], [%1], 16;" :: "r"(d), "l"(s))
#define CP_COMMIT()  asm volatile("cp.async.commit_group;" ::: "memory")
#define CP_WAIT1()   asm volatile("cp.async.wait_group 1;" ::: "memory")
#define CP_WAIT0()   asm volatile("cp.async.wait_group 0;" ::: "memory")

__device__ __forceinline__ uint32_t smem_u32(const void* p) {
    uint32_t a;
    asm("{ .reg .u64 t; cvta.to.shared.u64 t, %1; cvt.u32.u64 %0, t; }" : "=r"(a) : "l"(p));
    return a;
}
__device__ __forceinline__ ull enc_key(float f, int idx) {
    uint32_t u = __float_as_uint(f);
    u = (u & 0x80000000u) ? ~u : (u | 0x80000000u);
    return ((ull)u << 32) | (uint32_t)idx;
}
__device__ __forceinline__ float dec_val(ull k) {
    uint32_t e = (uint32_t)(k >> 32);
    uint32_t u = (e & 0x80000000u) ? (e ^ 0x80000000u) : ~e;
    return __uint_as_float(u);
}

__device__ __forceinline__ float blockReduceSum(float v) {
    __shared__ float sw[32];
    int lane = threadIdx.x & 31, w = threadIdx.x >> 5;
    #pragma unroll
    for (int o = 16; o; o >>= 1) v += __shfl_xor_sync(~0u, v, o);
    if (lane == 0) sw[w] = v;
    __syncthreads();
    int nw = (blockDim.x + 31) >> 5;
    v = (threadIdx.x < nw) ? sw[threadIdx.x] : 0.f;
    if (w == 0) {
        #pragma unroll
        for (int o = 16; o; o >>= 1) v += __shfl_xor_sync(~0u, v, o);
    }
    return v;
}

// ---------------- kernels ----------------
__global__ void k_init() { if (threadIdx.x < 32) g_acc[threadIdx.x] = 0.0; }
__global__ void k_keyinit() {
    int i = blockIdx.x * blockDim.x + threadIdx.x;
    if (i < 2 * B * HW) ((ull*)g_key)[i] = ~0ull;
}

__global__ void k_norms(const float* __restrict__ s1, const float* __restrict__ s2) {
    int b = blockIdx.x, p = threadIdx.x;
    const float* src = blockIdx.y ? s2 : s1;
    float*       dst = blockIdx.y ? g_b2 : g_a2;
    const float* base = src + (size_t)b * C * HW + p;
    float s = 0.f;
    #pragma unroll 8
    for (int c = 0; c < C; c++) { float v = base[(size_t)c * HW]; s += v * v; }
    dst[b * HW + p] = s;
}

#define LDW     136               // 136 % 32 == 8 -> conflict-free LDS.128 fragment fetch
#define MATW    (32*LDW)
#define SSTRIDE (2*MATW)
#define GSMEM   (2 * SSTRIDE * 4)

// logical->physical remap (read side only; cp.async stores stay linear):
//   A frag (i, row in {gr, gr+8}) <-> m = wm + (i>>1)*32 + gr*4 + (i&1)*2 + (row>=8)
//   B frag j, C col (2gc+rb)      <-> n = wn + 8*gc + 4*rb + j
// fragment fetch per 8-k step: 4x LDS.128 (A) + 2x LDS.128 (B)
#define FRAG_FETCH(As, Bs, ks)                                                     \
    uint4 a_lo0 = *(const uint4*)&As[(ks + gc    ) * LDW + wm      + gr * 4];      \
    uint4 a_lo1 = *(const uint4*)&As[(ks + gc    ) * LDW + wm + 32 + gr * 4];      \
    uint4 a_hi0 = *(const uint4*)&As[(ks + gc + 4) * LDW + wm      + gr * 4];      \
    uint4 a_hi1 = *(const uint4*)&As[(ks + gc + 4) * LDW + wm + 32 + gr * 4];      \
    uint4 b_lo  = *(const uint4*)&Bs[(ks + gc    ) * LDW + wn      + gr * 4];      \
    uint4 b_hi  = *(const uint4*)&Bs[(ks + gc + 4) * LDW + wn      + gr * 4];      \
    uint32_t af[4][4] = {                                                          \
        {a_lo0.x, a_lo0.y, a_hi0.x, a_hi0.y},                                      \
        {a_lo0.z, a_lo0.w, a_hi0.z, a_hi0.w},                                      \
        {a_lo1.x, a_lo1.y, a_hi1.x, a_hi1.y},                                      \
        {a_lo1.z, a_lo1.w, a_hi1.z, a_hi1.w},                                      \
    };                                                                             \
    uint32_t bf[4][2] = {                                                          \
        {b_lo.x, b_hi.x}, {b_lo.y, b_hi.y}, {b_lo.z, b_hi.z}, {b_lo.w, b_hi.w},   \
    };

// ---- fused tf32 GEMM + row/col argmin. CTA 128x128, 8 warps (2m x 4n) ----
__global__ void __launch_bounds__(256, 2) k_gemm_fused(const float* __restrict__ s1,
                                                       const float* __restrict__ s2) {
    extern __shared__ uint32_t dyn[];
    int b  = blockIdx.z;
    int m0 = blockIdx.y * 128, n0 = blockIdx.x * 128;
    int tid = threadIdx.x, w = tid >> 5, lane = tid & 31;
    int wm = (w & 1) * 64, wn = (w >> 1) * 32;
    int gr = lane >> 2, gc = lane & 3;

    const float* Ag = s1 + (size_t)b * C * HW;
    const float* Bg = s2 + (size_t)b * C * HW;
    uint32_t sbase = smem_u32(dyn);

    int rowv[4], colA[4], colB[4];
    #pragma unroll
    for (int t = 0; t < 4; t++) {
        int v = tid + t * 256;
        rowv[t] = v >> 5;
        int col = (v & 31) * 4;
        int ca = m0 + col; if (ca > HW - 4) ca = HW - 4;
        int cb = n0 + col; if (cb > HW - 4) cb = HW - 4;
        colA[t] = ca; colB[t] = cb;
    }
    auto issue_chunk = [&](int s, int stage) {
        int k0 = s * KC;
        uint32_t sA = sbase + stage * (SSTRIDE * 4);
        uint32_t sB = sA + MATW * 4;
        #pragma unroll
        for (int t = 0; t < 4; t++) {
            int v = tid + t * 256;
            uint32_t so = ((v >> 5) * LDW + (v & 31) * 4) * 4;
            CP_A16(sA + so, (const char*)&Ag[(size_t)(k0 + rowv[t]) * HW + colA[t]]);
            CP_A16(sB + so, (const char*)&Bg[(size_t)(k0 + rowv[t]) * HW + colB[t]]);
        }
        CP_COMMIT();
    };

    float acc[4][4][4] = {};
    issue_chunk(0, 0);
    for (int s = 0; s < NCH; s++) {
        if (s + 1 < NCH) { issue_chunk(s + 1, (s + 1) & 1); CP_WAIT1(); }
        else             { CP_WAIT0(); }
        __syncthreads();
        const uint32_t* As = dyn + (s & 1) * SSTRIDE;
        const uint32_t* Bs = As + MATW;
        #pragma unroll
        for (int ks = 0; ks < KC; ks += 8) {
            FRAG_FETCH(As, Bs, ks)
            #pragma unroll
            for (int i = 0; i < 4; i++)
                #pragma unroll
                for (int j = 0; j < 4; j++)
                    mma_tf32(acc[i][j], af[i], bf[j]);
        }
        __syncthreads();
    }

    // ---- fused argmin epilogue (remapped indices) ----
    ull* rkey = (ull*)dyn;
    ull* ckey = rkey + 128;
    if (tid < 128) { rkey[tid] = ~0ull; ckey[tid] = ~0ull; }
    __syncthreads();

    const float* a2p = g_a2 + b * HW;
    const float* b2p = g_b2 + b * HW;

    // row candidates: each (i, half) is one local m; min over (j, rb)
    #pragma unroll
    for (int i = 0; i < 4; i++) {
        int mbase = wm + (i >> 1) * 32 + gr * 4 + (i & 1) * 2;
        #pragma unroll
        for (int half = 0; half < 2; half++) {
            int ml = mbase + half;
            ull rb_ = ~0ull;
            #pragma unroll
            for (int j = 0; j < 4; j++)
                #pragma unroll
                for (int rb = 0; rb < 2; rb++) {
                    int n_g = n0 + wn + 8 * gc + 4 * rb + j;
                    if (n_g < HW) {
                        ull k = enc_key(b2p[n_g] - 2.f * acc[i][j][half * 2 + rb], n_g);
                        if (k < rb_) rb_ = k;
                    }
                }
            if (rb_ != ~0ull) atomicMin(&rkey[ml], rb_);
        }
    }
    // col candidates: each (j, rb) is one local n; min over (i, half)
    #pragma unroll
    for (int j = 0; j < 4; j++)
        #pragma unroll
        for (int rb = 0; rb < 2; rb++) {
            int nl = wn + 8 * gc + 4 * rb + j;
            ull cbest = ~0ull;
            #pragma unroll
            for (int i = 0; i < 4; i++) {
                int mbase = m0 + wm + (i >> 1) * 32 + gr * 4 + (i & 1) * 2;
                #pragma unroll
                for (int half = 0; half < 2; half++) {
                    int m_g = mbase + half;
                    if (m_g < HW) {
                        ull k = enc_key(a2p[m_g] - 2.f * acc[i][j][half * 2 + rb], m_g);
                        if (k < cbest) cbest = k;
                    }
                }
            }
            if (cbest != ~0ull) atomicMin(&ckey[nl], cbest);
        }
    __syncthreads();
    if (tid < 128) {
        int m = m0 + tid;
        if (m < HW) atomicMin(&g_key[0][b * HW + m], rkey[tid]);
    } else {
        int n = n0 + tid - 128;
        if (n < HW) atomicMin(&g_key[1][b * HW + n], ckey[tid - 128]);
    }
}

// ---- tf32 MMA Gram for the 4 big X tensors: S[t] = X^T X, upper 128x128 tiles ----
__global__ void __launch_bounds__(256, 2) k_gram_mma() {
    extern __shared__ uint32_t dyn[];
    int t = blockIdx.y;
    const float* X = g_X[t];
    int idx = blockIdx.x, ti = 0;
    while (idx >= 6 - ti) { idx -= 6 - ti; ti++; }
    int tj = ti + idx;
    int i0 = ti * 128, j0 = tj * 128;

    int tid = threadIdx.x, w = tid >> 5, lane = tid & 31;
    int wm = (w & 1) * 64, wn = (w >> 1) * 32;
    int gr = lane >> 2, gc = lane & 3;
    uint32_t sbase = smem_u32(dyn);

    auto issue_chunk = [&](int s, int stage) {
        int k0 = s * KC;
        uint32_t sA = sbase + stage * (SSTRIDE * 4);
        uint32_t sB = sA + MATW * 4;
        #pragma unroll
        for (int tt = 0; tt < 4; tt++) {
            int v = tid + tt * 256;
            int row = v >> 5, col = (v & 31) * 4;
            uint32_t so = (row * LDW + col) * 4;
            CP_A16(sA + so, (const char*)&X[(size_t)(k0 + row) * C + i0 + col]);
            CP_A16(sB + so, (const char*)&X[(size_t)(k0 + row) * C + j0 + col]);
        }
        CP_COMMIT();
    };

    float acc[4][4][4] = {};
    issue_chunk(0, 0);
    for (int s = 0; s < NCH2; s++) {
        if (s + 1 < NCH2) { issue_chunk(s + 1, (s + 1) & 1); CP_WAIT1(); }
        else              { CP_WAIT0(); }
        __syncthreads();
        const uint32_t* As = dyn + (s & 1) * SSTRIDE;
        const uint32_t* Bs = As + MATW;
        #pragma unroll
        for (int ks = 0; ks < KC; ks += 8) {
            FRAG_FETCH(As, Bs, ks)
            #pragma unroll
            for (int i = 0; i < 4; i++)
                #pragma unroll
                for (int j = 0; j < 4; j++)
                    mma_tf32(acc[i][j], af[i], bf[j]);
        }
        __syncthreads();
    }

    float* Sp = g_S[t];
    #pragma unroll
    for (int i = 0; i < 4; i++) {
        int mbase = i0 + wm + (i >> 1) * 32 + gr * 4 + (i & 1) * 2;
        #pragma unroll
        for (int j = 0; j < 4; j++)
            #pragma unroll
            for (int rb = 0; rb < 2; rb++) {
                int c2 = j0 + wn + 8 * gc + 4 * rb + j;
                Sp[(size_t)mbase * C + c2]       = acc[i][j][rb];
                Sp[(size_t)(mbase + 1) * C + c2] = acc[i][j][2 + rb];
            }
    }
}

// rank-based top-50 smallest d2 (ties -> lowest index)
__global__ void k_select() {
    int b = blockIdx.x, dir = blockIdx.y;
    __shared__ float sd[HW];
    __shared__ int   sn[HW];
    int i = threadIdx.x;
    ull key = g_key[dir][b * HW + i];
    const float* own = dir ? g_b2 : g_a2;
    float d2 = own[b * HW + i] + dec_val(key);
    if (d2 < 0.f) d2 = 0.f;
    sd[i] = d2;
    sn[i] = (int)(uint32_t)key;
    __syncthreads();
    float di = sd[i];
    int rank = 0;
    for (int j = 0; j < HW; j++) {
        float dj = sd[j];
        rank += (dj < di) || (dj == di && j < i);
    }
    if (rank < NM) {
        g_sel_in[dir][b * NM + rank] = i;
        g_sel_c [dir][b * NM + rank] = sn[i];
    }
}

__global__ void k_gather(const float* __restrict__ s1, const float* __restrict__ s2) {
    int k = blockIdx.x, b = blockIdx.y, dir = blockIdx.z;
    const float* srcin = dir ? s2 : s1;
    const float* srcc  = dir ? s1 : s2;
    int pin = g_sel_in[dir][b * NM + k];
    int pc  = g_sel_c [dir][b * NM + k];
    float* Xin = g_X[dir * 2 + 0];
    float* Xc  = g_X[dir * 2 + 1];
    int row = b * NM + k;
    float lsum = 0.f;
    for (int c = threadIdx.x; c < C; c += 256) {
        float vi = srcin[((size_t)b * C + c) * HW + pin];
        float vc = srcc [((size_t)b * C + c) * HW + pc];
        Xin[(size_t)row * C + c] = vi;
        Xc [(size_t)row * C + c] = vc;
        float d = vi - vc; lsum += d * d;
    }
    float tot = blockReduceSum(lsum);
    if (threadIdx.x == 0) atomicAdd(&g_acc[1 + dir], (double)tot);
}

__global__ void k_pooled_inv(const float* __restrict__ p1, const float* __restrict__ p2) {
    float lsum = 0.f;
    for (int i = blockIdx.x * blockDim.x + threadIdx.x; i < B * C; i += gridDim.x * blockDim.x) {
        float d = p1[i] - p2[i]; lsum += d * d;
    }
    float tot = blockReduceSum(lsum);
    if (threadIdx.x == 0) atomicAdd(&g_acc[0], (double)tot);
}

__device__ __forceinline__ const float* tensor_ptr(int t, const float* p1, const float* p2) {
    if (t < 4) return g_X[t];
    return (t == 4) ? p1 : p2;
}
__device__ __forceinline__ int tensor_n(int t) { return (t < 4) ? NSEL : B; }

__global__ void k_colsum_part(const float* __restrict__ p1, const float* __restrict__ p2) {
    int t = blockIdx.x, chunk = blockIdx.y, c = threadIdx.x;
    const float* X = tensor_ptr(t, p1, p2);
    int n = tensor_n(t);
    int step = n / 16;
    int n0 = chunk * step, n1 = n0 + step;
    float s = 0.f;
    for (int i = n0; i < n1; i++) s += X[(size_t)i * C + c];
    g_csp[t][chunk][c] = s;
}
__global__ void k_colsum_fin() {
    int t = blockIdx.x, c = threadIdx.x;
    float s = 0.f;
    #pragma unroll
    for (int k = 0; k < 16; k++) s += g_csp[t][k][c];
    g_colsum[t][c] = s;
}

// exact fp32 Gram for the 2 pooled tensors (n=64), upper 64x64 tiles
__global__ void __launch_bounds__(256) k_gram(const float* __restrict__ p1,
                                              const float* __restrict__ p2) {
    int t = 4 + blockIdx.y;
    const float* X = tensor_ptr(t, p1, p2);
    int n = tensor_n(t);
    int idx = blockIdx.x, ti = 0;
    while (idx >= 12 - ti) { idx -= 12 - ti; ti++; }
    int tj = ti + idx;
    int i0 = ti * 64, j0 = tj * 64;

    __shared__ float As[16][64], Bs[16][64];
    int tid = threadIdx.x;
    int tx = tid & 15, ty = tid >> 4;
    int lk = tid >> 4, lo = (tid & 15) * 4;
    float acc[4][4] = {};
    for (int k0 = 0; k0 < n; k0 += 16) {
        *(float4*)&As[lk][lo] = *(const float4*)&X[(size_t)(k0 + lk) * C + i0 + lo];
        *(float4*)&Bs[lk][lo] = *(const float4*)&X[(size_t)(k0 + lk) * C + j0 + lo];
        __syncthreads();
        #pragma unroll
        for (int kk = 0; kk < 16; kk++) {
            float a[4], bb[4];
            *(float4*)a  = *(float4*)&As[kk][ty * 4];
            *(float4*)bb = *(float4*)&Bs[kk][tx * 4];
            #pragma unroll
            for (int i = 0; i < 4; i++)
                #pragma unroll
                for (int j = 0; j < 4; j++) acc[i][j] += a[i] * bb[j];
        }
        __syncthreads();
    }
    float* Sp = g_S[t];
    #pragma unroll
    for (int i = 0; i < 4; i++) {
        int c1 = i0 + ty * 4 + i;
        *(float4*)&Sp[(size_t)c1 * C + j0 + tx * 4] = *(float4*)acc[i];
    }
}

__global__ void k_std() {
    int t = blockIdx.x, c = threadIdx.x;
    float n  = (float)tensor_n(t);
    float mu = g_colsum[t][c] / n;
    float Scc = g_S[t][(size_t)c * C + c];
    float var = (Scc - n * mu * mu) / (n - 1.f);
    float sd  = sqrtf(var + EPSV);
    float contrib = fmaxf(1.f - sd, 0.f);
    float tot = blockReduceSum(contrib);
    if (threadIdx.x == 0) atomicAdd(&g_acc[3 + t], (double)tot);
}

__global__ void k_cov() {
    int t = blockIdx.y;
    float n = (float)tensor_n(t);
    float inv_nm1 = 1.f / (n - 1.f);
    int idx = blockIdx.x, ti = 0;
    while (idx >= 12 - ti) { idx -= 12 - ti; ti++; }
    int tj = ti + idx;
    int i0 = ti * 64, j0 = tj * 64;
    const float* Sp = g_S[t];
    float lsum = 0.f;
    #pragma unroll
    for (int it = 0; it < 16; it++) {
        int e = it * 256 + threadIdx.x;
        int r = e >> 6, cc = e & 63;
        int c1 = i0 + r, c2 = j0 + cc;
        if (c2 > c1) {
            float mu1 = g_colsum[t][c1] / n;
            float mu2 = g_colsum[t][c2] / n;
            float cov = (Sp[(size_t)c1 * C + c2] - n * mu1 * mu2) * inv_nm1;
            lsum += 2.f * cov * cov;
        }
    }
    float tot = blockReduceSum(lsum);
    if (threadIdx.x == 0) atomicAdd(&g_acc[10 + t], (double)tot);
}

__global__ void k_final(float* __restrict__ out) {
    double inv_g = g_acc[0] / (double)(B * C);
    double inv1  = g_acc[1] / (double)((size_t)NSEL * C);
    double inv2  = g_acc[2] / (double)((size_t)NSEL * C);
    double stdt[6], covt[6];
    for (int t = 0; t < 6; t++) {
        stdt[t] = (g_acc[3 + t] / (double)C) * 0.5;
        covt[t] = g_acc[10 + t] / (double)C;
    }
    double glob = 25.0 * inv_g + 25.0 * (stdt[4] + stdt[5]) + (covt[4] + covt[5]);
    double loc  = 0.5 * (25.0 * inv1 + 25.0 * inv2)
                + 0.5 * (25.0 * (stdt[0] + stdt[1]) + 25.0 * (stdt[2] + stdt[3]))
                + 0.5 * ((covt[0] + covt[1]) + (covt[2] + covt[3]));
    out[0] = (float)(0.5 * glob + 0.5 * loc);
}

// ---------------- launch ----------------
extern "C" void kernel_launch(void* const* d_in, const int* in_sizes, int n_in,
                              void* d_out, int out_size) {
    const float* s1 = (const float*)d_in[0];
    const float* p1 = (const float*)d_in[1];
    const float* s2 = (const float*)d_in[2];
    const float* p2 = (const float*)d_in[3];
    float* out = (float*)d_out;

    cudaFuncSetAttribute(k_gemm_fused, cudaFuncAttributeMaxDynamicSharedMemorySize, GSMEM);
    cudaFuncSetAttribute(k_gram_mma,   cudaFuncAttributeMaxDynamicSharedMemorySize, GSMEM);

    k_init<<<1, 32>>>();
    k_keyinit<<<(2 * B * HW + 255) / 256, 256>>>();
    k_norms<<<dim3(B, 2), HW>>>(s1, s2);
    k_gemm_fused<<<dim3(5, 5, B), 256, GSMEM>>>(s1, s2);
    k_select<<<dim3(B, 2), HW>>>();
    k_gather<<<dim3(NM, B, 2), 256>>>(s1, s2);
    k_pooled_inv<<<48, 256>>>(p1, p2);
    k_colsum_part<<<dim3(6, 16), C>>>(p1, p2);
    k_colsum_fin<<<6, C>>>();
    k_gram_mma<<<dim3(21, 4), 256, GSMEM>>>();
    k_gram<<<dim3(78, 2), 256>>>(p1, p2);
    k_std<<<6, C>>>();
    k_cov<<<dim3(78, 6), 256>>>();
    k_final<<<1, 1>>>(out);
}